// round 2
// baseline (speedup 1.0000x reference)
#include <cuda_runtime.h>
#include <cstdint>

#define B_      32
#define N_      500
#define D_      2048
#define K_      128
#define SIGMA   0.05f
#define THREADS 256

// monotone float -> uint mapping (bigger float -> bigger uint)
__device__ __forceinline__ unsigned int f2u(float f) {
    unsigned int u = __float_as_uint(f);
    return u ^ (((unsigned int)((int)u >> 31)) | 0x80000000u);
}

// Exclusive block scan over 256 threads via shuffles. Also returns block total.
// Works on packed 16+16 values (no cross-half overflow for totals < 65536).
__device__ __forceinline__ unsigned int block_scan_excl(unsigned int v,
                                                        unsigned int* warpSums,
                                                        unsigned int* total) {
    const int lane = threadIdx.x & 31;
    const int wid  = threadIdx.x >> 5;
    unsigned int x = v;
    #pragma unroll
    for (int o = 1; o < 32; o <<= 1) {
        unsigned int y = __shfl_up_sync(0xffffffffu, x, o);
        if (lane >= o) x += y;
    }
    if (lane == 31) warpSums[wid] = x;          // warp inclusive totals
    __syncthreads();
    if (wid == 0 && lane < 8) {
        unsigned int s = warpSums[lane];
        #pragma unroll
        for (int o = 1; o < 8; o <<= 1) {
            unsigned int y = __shfl_up_sync(0xffu, s, o);
            if (lane >= o) s += y;
        }
        warpSums[lane] = s;                     // inclusive across warps
    }
    __syncthreads();
    unsigned int base = (wid > 0) ? warpSums[wid - 1] : 0u;
    unsigned int tot  = warpSums[7];
    __syncthreads();                            // protect warpSums for next call
    *total = tot;
    return base + x - v;                        // exclusive prefix
}

__global__ void zero_kernel(float4* __restrict__ p, int n4) {
    int i = blockIdx.x * blockDim.x + threadIdx.x;
    int stride = gridDim.x * blockDim.x;
    float4 z = make_float4(0.f, 0.f, 0.f, 0.f);
    for (; i < n4; i += stride) p[i] = z;
}

__global__ __launch_bounds__(THREADS)
void perturbed_topk_kernel(const float* __restrict__ x,
                           const float* __restrict__ noise,
                           float* __restrict__ ind,    // (B,K,D) or null
                           float* __restrict__ idxf)   // (B,N,K) or null
{
    __shared__ unsigned int hist[4096];
    __shared__ unsigned int warpSums[8];
    __shared__ unsigned int sh_sel;
    __shared__ unsigned int sh_krem;

    const int t = threadIdx.x;
    const int b = blockIdx.x / N_;

    // ---- load + perturb into REGISTERS (two segments of 4 contiguous elems) ----
    const float4* xv = (const float4*)(x + (size_t)b * D_);
    const float4* nv = (const float4*)(noise + (size_t)blockIdx.x * D_);
    unsigned int k0[4], k1[4];
    {
        float4 xx = xv[t];
        float4 nn = nv[t];
        k0[0] = f2u(fmaf(SIGMA, nn.x, xx.x));
        k0[1] = f2u(fmaf(SIGMA, nn.y, xx.y));
        k0[2] = f2u(fmaf(SIGMA, nn.z, xx.z));
        k0[3] = f2u(fmaf(SIGMA, nn.w, xx.w));
        xx = xv[t + THREADS];
        nn = nv[t + THREADS];
        k1[0] = f2u(fmaf(SIGMA, nn.x, xx.x));
        k1[1] = f2u(fmaf(SIGMA, nn.y, xx.y));
        k1[2] = f2u(fmaf(SIGMA, nn.z, xx.z));
        k1[3] = f2u(fmaf(SIGMA, nn.w, xx.w));
    }

    // ---- 3-pass radix select (12 / 12 / 8 bits) ----
    unsigned int prefHigh = 0;
    unsigned int maskHigh = 0;
    unsigned int krem = K_;

    const int shifts[3] = {20, 8, 0};
    const int binsArr[3] = {4096, 4096, 256};

    #pragma unroll
    for (int pass = 0; pass < 3; pass++) {
        const int shift = shifts[pass];
        const int bins  = binsArr[pass];
        const int bpt   = bins / THREADS;       // 16, 16, 1
        const unsigned int dmask = (unsigned int)(bins - 1);

        // clear
        #pragma unroll
        for (int i = 0; i < 16; i++) {
            if (i < bpt) hist[t + i * THREADS] = 0u;
        }
        __syncthreads();

        // accumulate candidates
        #pragma unroll
        for (int i = 0; i < 4; i++) {
            unsigned int k = k0[i];
            if ((k & maskHigh) == prefHigh)
                atomicAdd(&hist[(k >> shift) & dmask], 1u);
            k = k1[i];
            if ((k & maskHigh) == prefHigh)
                atomicAdd(&hist[(k >> shift) & dmask], 1u);
        }
        __syncthreads();

        // digit find via suffix counts: suffix(j) = total - excl_prefix(j)
        unsigned int c[16];
        unsigned int lsum = 0;
        #pragma unroll
        for (int i = 0; i < 16; i++) {
            if (i < bpt) { c[i] = hist[t * bpt + i]; lsum += c[i]; }
        }
        unsigned int tot;
        unsigned int run = block_scan_excl(lsum, warpSums, &tot);
        #pragma unroll
        for (int i = 0; i < 16; i++) {
            if (i < bpt) {
                unsigned int sfx   = tot - run;        // suffix incl this bin
                unsigned int after = sfx - c[i];       // suffix of next bin
                if (sfx >= krem && after < krem) {
                    sh_sel  = (unsigned int)(t * bpt + i);
                    sh_krem = krem - after;
                }
                run += c[i];
            }
        }
        __syncthreads();
        prefHigh |= (sh_sel << shift);
        maskHigh |= (dmask << shift);
        krem = sh_krem;
        __syncthreads();
    }

    const unsigned int T = prefHigh;   // exact K-th key
    const unsigned int R = krem;       // # of ==T keys to take (lowest indices first)

    // ---- counts per segment ----
    unsigned int gt0 = 0, eq0 = 0, gt1 = 0, eq1 = 0;
    #pragma unroll
    for (int i = 0; i < 4; i++) {
        gt0 += (k0[i] > T);  eq0 += (k0[i] == T);
        gt1 += (k1[i] > T);  eq1 += (k1[i] == T);
    }

    // packed scans: low16 = segment0 (elems 0..1023), high16 = segment1
    unsigned int eqTot;
    unsigned int eqPref = block_scan_excl(eq0 | (eq1 << 16), warpSums, &eqTot);
    unsigned int eqBefore0 = eqPref & 0xFFFFu;
    unsigned int eqBefore1 = (eqTot & 0xFFFFu) + (eqPref >> 16);

    int take0 = (int)R - (int)eqBefore0;
    if (take0 < 0) take0 = 0;
    if (take0 > (int)eq0) take0 = (int)eq0;
    int take1 = (int)R - (int)eqBefore1;
    if (take1 < 0) take1 = 0;
    if (take1 > (int)eq1) take1 = (int)eq1;

    unsigned int sel0 = gt0 + (unsigned int)take0;
    unsigned int sel1 = gt1 + (unsigned int)take1;
    unsigned int selTot;
    unsigned int selPref = block_scan_excl(sel0 | (sel1 << 16), warpSums, &selTot);
    unsigned int base0 = selPref & 0xFFFFu;
    unsigned int base1 = (selTot & 0xFFFFu) + (selPref >> 16);

    // ---- emit in ascending index order ----
    const size_t idxBase = (size_t)blockIdx.x * K_;
    const float inv_n = 1.0f / (float)N_;

    unsigned int j = base0, eqRank = eqBefore0;
    #pragma unroll
    for (int i = 0; i < 4; i++) {
        int e = 4 * t + i;
        unsigned int k = k0[i];
        bool isEq = (k == T);
        bool sel  = (k > T) || (isEq && (eqRank < R));
        eqRank += isEq ? 1u : 0u;
        if (sel) {
            if (idxf) idxf[idxBase + j] = (float)e;
            if (ind)  atomicAdd(&ind[((size_t)b * K_ + j) * D_ + e], inv_n);
            j++;
        }
    }
    j = base1; eqRank = eqBefore1;
    #pragma unroll
    for (int i = 0; i < 4; i++) {
        int e = 1024 + 4 * t + i;
        unsigned int k = k1[i];
        bool isEq = (k == T);
        bool sel  = (k > T) || (isEq && (eqRank < R));
        eqRank += isEq ? 1u : 0u;
        if (sel) {
            if (idxf) idxf[idxBase + j] = (float)e;
            if (ind)  atomicAdd(&ind[((size_t)b * K_ + j) * D_ + e], inv_n);
            j++;
        }
    }
}

extern "C" void kernel_launch(void* const* d_in, const int* in_sizes, int n_in,
                              void* d_out, int out_size) {
    const float* x     = (const float*)d_in[0];
    const float* noise = (const float*)d_in[1];
    if (n_in >= 2 && in_sizes[0] != B_ * D_) {
        x     = (const float*)d_in[1];
        noise = (const float*)d_in[0];
    }

    const long long IND = (long long)B_ * K_ * D_;   // 8388608
    const long long IDX = (long long)B_ * N_ * K_;   // 2048000

    float* ind  = nullptr;
    float* idxf = nullptr;
    if ((long long)out_size >= IND + IDX) {
        ind  = (float*)d_out;
        idxf = (float*)d_out + IND;
    } else if ((long long)out_size == IND) {
        ind = (float*)d_out;
    } else if ((long long)out_size == IDX) {
        idxf = (float*)d_out;
    } else {
        ind = (float*)d_out;
    }

    if (ind) zero_kernel<<<2048, 256>>>((float4*)ind, (int)(IND / 4));
    perturbed_topk_kernel<<<B_ * N_, THREADS>>>(x, noise, ind, idxf);
}

// round 3
// speedup vs baseline: 2.4155x; 2.4155x over previous
#include <cuda_runtime.h>
#include <cstdint>

#define B_      32
#define N_      500
#define D_      2048
#define K_      128
#define SIGMA   0.05f
#define THREADS 512          // 4 elements per thread, one contiguous float4

// monotone float -> uint mapping (bigger float -> bigger uint)
__device__ __forceinline__ unsigned int f2u(float f) {
    unsigned int u = __float_as_uint(f);
    return u ^ (((unsigned int)((int)u >> 31)) | 0x80000000u);
}

// Exclusive block scan over 512 threads via shuffles; also returns block total.
__device__ __forceinline__ unsigned int block_scan_excl(unsigned int v,
                                                        unsigned int* warpSums,
                                                        unsigned int* total) {
    const int lane = threadIdx.x & 31;
    const int wid  = threadIdx.x >> 5;          // 0..15
    unsigned int x = v;
    #pragma unroll
    for (int o = 1; o < 32; o <<= 1) {
        unsigned int y = __shfl_up_sync(0xffffffffu, x, o);
        if (lane >= o) x += y;
    }
    if (lane == 31) warpSums[wid] = x;          // warp inclusive totals
    __syncthreads();
    if (wid == 0 && lane < 16) {
        unsigned int s = warpSums[lane];
        #pragma unroll
        for (int o = 1; o < 16; o <<= 1) {
            unsigned int y = __shfl_up_sync(0xffffu, s, o);
            if (lane >= o) s += y;
        }
        warpSums[lane] = s;                     // inclusive across warps
    }
    __syncthreads();
    unsigned int base = (wid > 0) ? warpSums[wid - 1] : 0u;
    unsigned int tot  = warpSums[15];
    __syncthreads();                            // protect warpSums for reuse
    *total = tot;
    return base + x - v;                        // exclusive prefix
}

__global__ void zero_kernel(float4* __restrict__ p, int n4) {
    int i = blockIdx.x * blockDim.x + threadIdx.x;
    int stride = gridDim.x * blockDim.x;
    float4 z = make_float4(0.f, 0.f, 0.f, 0.f);
    for (; i < n4; i += stride) p[i] = z;
}

__global__ __launch_bounds__(THREADS, 4)
void perturbed_topk_kernel(const float* __restrict__ x,
                           const float* __restrict__ noise,
                           float* __restrict__ ind,    // (B,K,D) or null
                           float* __restrict__ idxf)   // (B,N,K) or null
{
    __shared__ unsigned int hist[256];
    __shared__ unsigned int warpSums[16];
    __shared__ unsigned int sh_sel;
    __shared__ unsigned int sh_krem;

    const int t = threadIdx.x;
    const int b = blockIdx.x / N_;

    // ---- load + perturb into registers: thread t owns elems 4t..4t+3 ----
    unsigned int k[4];
    {
        float4 xx = ((const float4*)(x + (size_t)b * D_))[t];
        float4 nn = ((const float4*)(noise + (size_t)blockIdx.x * D_))[t];
        k[0] = f2u(fmaf(SIGMA, nn.x, xx.x));
        k[1] = f2u(fmaf(SIGMA, nn.y, xx.y));
        k[2] = f2u(fmaf(SIGMA, nn.z, xx.z));
        k[3] = f2u(fmaf(SIGMA, nn.w, xx.w));
    }

    // ---- 4-pass 8-bit radix select ----
    unsigned int prefHigh = 0;
    unsigned int maskHigh = 0;
    unsigned int krem = K_;

    #pragma unroll
    for (int pass = 0; pass < 4; pass++) {
        const int shift = 24 - pass * 8;

        if (t < 256) hist[t] = 0u;
        __syncthreads();

        #pragma unroll
        for (int i = 0; i < 4; i++) {
            unsigned int kk = k[i];
            if ((kk & maskHigh) == prefHigh)
                atomicAdd(&hist[(kk >> shift) & 0xFFu], 1u);
        }
        __syncthreads();

        // digit find via suffix counts: suffix(j) = total - excl_prefix(j)
        unsigned int c = (t < 256) ? hist[t] : 0u;
        unsigned int tot;
        unsigned int pref = block_scan_excl(c, warpSums, &tot);
        if (t < 256) {
            unsigned int sfx   = tot - pref;       // count of keys in bins >= t
            unsigned int after = sfx - c;          // count in bins > t
            if (sfx >= krem && after < krem) {     // exactly one thread
                sh_sel  = (unsigned int)t;
                sh_krem = krem - after;
            }
        }
        __syncthreads();
        prefHigh |= (sh_sel << shift);
        maskHigh |= (0xFFu << shift);
        krem = sh_krem;
        __syncthreads();
    }

    const unsigned int T = prefHigh;   // exact K-th key
    const unsigned int R = krem;       // # of ==T keys to take (lowest indices first)

    // ---- count, scan, compact in ascending index order ----
    unsigned int gt = 0, eq = 0;
    #pragma unroll
    for (int i = 0; i < 4; i++) {
        gt += (k[i] > T);
        eq += (k[i] == T);
    }
    unsigned int eqTot;
    unsigned int eqBefore = block_scan_excl(eq, warpSums, &eqTot);

    int take = (int)R - (int)eqBefore;
    if (take < 0) take = 0;
    if (take > (int)eq) take = (int)eq;

    unsigned int selTot;
    unsigned int base = block_scan_excl(gt + (unsigned int)take, warpSums, &selTot);

    const size_t idxBase = (size_t)blockIdx.x * K_;
    const float inv_n = 1.0f / (float)N_;

    unsigned int j = base, eqRank = eqBefore;
    #pragma unroll
    for (int i = 0; i < 4; i++) {
        int e = 4 * t + i;
        unsigned int kk = k[i];
        bool isEq = (kk == T);
        bool sel  = (kk > T) || (isEq && (eqRank < R));
        eqRank += isEq ? 1u : 0u;
        if (sel) {
            if (idxf) idxf[idxBase + j] = (float)e;
            if (ind)  atomicAdd(&ind[((size_t)b * K_ + j) * D_ + e], inv_n);
            j++;
        }
    }
}

extern "C" void kernel_launch(void* const* d_in, const int* in_sizes, int n_in,
                              void* d_out, int out_size) {
    const float* x     = (const float*)d_in[0];
    const float* noise = (const float*)d_in[1];
    if (n_in >= 2 && in_sizes[0] != B_ * D_) {
        x     = (const float*)d_in[1];
        noise = (const float*)d_in[0];
    }

    const long long IND = (long long)B_ * K_ * D_;   // 8388608
    const long long IDX = (long long)B_ * N_ * K_;   // 2048000

    float* ind  = nullptr;
    float* idxf = nullptr;
    if ((long long)out_size >= IND + IDX) {
        ind  = (float*)d_out;
        idxf = (float*)d_out + IND;
    } else if ((long long)out_size == IND) {
        ind = (float*)d_out;
    } else if ((long long)out_size == IDX) {
        idxf = (float*)d_out;
    } else {
        ind = (float*)d_out;
    }

    if (ind) zero_kernel<<<2048, 256>>>((float4*)ind, (int)(IND / 4));
    perturbed_topk_kernel<<<B_ * N_, THREADS>>>(x, noise, ind, idxf);
}

// round 4
// speedup vs baseline: 2.8037x; 1.1607x over previous
#include <cuda_runtime.h>
#include <cstdint>

#define B_      32
#define N_      500
#define D_      2048
#define K_      128
#define SIGMA   0.05f
#define THREADS 512          // 4 elements per thread, one contiguous float4

// monotone float -> uint mapping (bigger float -> bigger uint)
__device__ __forceinline__ unsigned int f2u(float f) {
    unsigned int u = __float_as_uint(f);
    return u ^ (((unsigned int)((int)u >> 31)) | 0x80000000u);
}

// Exclusive block scan over 512 threads via shuffles (packed 16+16 safe).
__device__ __forceinline__ unsigned int block_scan_excl(unsigned int v,
                                                        unsigned int* warpSums) {
    const int lane = threadIdx.x & 31;
    const int wid  = threadIdx.x >> 5;          // 0..15
    unsigned int x = v;
    #pragma unroll
    for (int o = 1; o < 32; o <<= 1) {
        unsigned int y = __shfl_up_sync(0xffffffffu, x, o);
        if (lane >= o) x += y;
    }
    if (lane == 31) warpSums[wid] = x;          // warp inclusive totals
    __syncthreads();
    if (wid == 0 && lane < 16) {
        unsigned int s = warpSums[lane];
        #pragma unroll
        for (int o = 1; o < 16; o <<= 1) {
            unsigned int y = __shfl_up_sync(0xffffu, s, o);
            if (lane >= o) s += y;
        }
        warpSums[lane] = s;                     // inclusive across warps
    }
    __syncthreads();
    unsigned int base = (wid > 0) ? warpSums[wid - 1] : 0u;
    return base + x - v;                        // exclusive prefix
}

__global__ void zero_kernel(float4* __restrict__ p, int n4) {
    int i = blockIdx.x * blockDim.x + threadIdx.x;
    int stride = gridDim.x * blockDim.x;
    float4 z = make_float4(0.f, 0.f, 0.f, 0.f);
    for (; i < n4; i += stride) p[i] = z;
}

__global__ __launch_bounds__(THREADS)
void perturbed_topk_kernel(const float* __restrict__ x,
                           const float* __restrict__ noise,
                           float* __restrict__ ind,    // (B,K,D) or null
                           float* __restrict__ idxf)   // (B,N,K) or null
{
    __shared__ unsigned int hist[256];
    __shared__ unsigned int warpSums[16];
    __shared__ unsigned int sh_sel;
    __shared__ unsigned int sh_krem;
    __shared__ unsigned int sh_done;

    const int t    = threadIdx.x;
    const int lane = t & 31;
    const int wid  = t >> 5;
    const int b    = blockIdx.x / N_;

    // ---- load + perturb into registers: thread t owns elems 4t..4t+3 ----
    unsigned int k[4];
    {
        float4 xx = ((const float4*)(x + (size_t)b * D_))[t];
        float4 nn = ((const float4*)(noise + (size_t)blockIdx.x * D_))[t];
        k[0] = f2u(fmaf(SIGMA, nn.x, xx.x));
        k[1] = f2u(fmaf(SIGMA, nn.y, xx.y));
        k[2] = f2u(fmaf(SIGMA, nn.z, xx.z));
        k[3] = f2u(fmaf(SIGMA, nn.w, xx.w));
    }

    // ---- 8-bit radix select with early exit ----
    unsigned int prefHigh = 0;
    unsigned int maskHigh = 0;
    unsigned int krem = K_;
    unsigned int done = 0;

    for (int pass = 0; pass < 4; pass++) {
        const int shift = 24 - pass * 8;

        if (t < 256) hist[t] = 0u;
        __syncthreads();

        #pragma unroll
        for (int i = 0; i < 4; i++) {
            unsigned int kk = k[i];
            if ((kk & maskHigh) == prefHigh)
                atomicAdd(&hist[(kk >> shift) & 0xFFu], 1u);
        }
        __syncthreads();

        // digit find on warp 0 only: lane owns bins [8*lane, 8*lane+8)
        if (wid == 0) {
            unsigned int c[8];
            unsigned int s = 0;
            #pragma unroll
            for (int i = 0; i < 8; i++) { c[i] = hist[lane * 8 + i]; s += c[i]; }
            unsigned int xs = s;
            #pragma unroll
            for (int o = 1; o < 32; o <<= 1) {
                unsigned int y = __shfl_up_sync(0xffffffffu, xs, o);
                if (lane >= o) xs += y;
            }
            unsigned int tot = __shfl_sync(0xffffffffu, xs, 31);
            unsigned int run = xs - s;                 // exclusive prefix of lane's bins
            #pragma unroll
            for (int i = 0; i < 8; i++) {
                unsigned int sfx   = tot - run;        // keys in bins >= this bin
                unsigned int after = sfx - c[i];       // keys in bins  > this bin
                if (sfx >= krem && after < krem) {     // exactly one (lane,i) matches
                    sh_sel  = (unsigned int)(lane * 8 + i);
                    sh_krem = krem - after;
                    sh_done = (sfx == krem);           // whole bin taken -> exact
                }
                run += c[i];
            }
        }
        __syncthreads();
        prefHigh |= (sh_sel << shift);
        maskHigh |= (0xFFu << shift);
        krem = sh_krem;
        done = sh_done;
        if (done) break;        // uniform across CTA
    }

    // T: exact K-th key (or bin prefix with zero low bits on early exit)
    // R: # of ==T keys to take, lowest indices first (K_ covers "take all" case)
    const unsigned int T = prefHigh;
    const unsigned int R = done ? (unsigned int)K_ : krem;

    // ---- counts + single packed scan (low16 = gt, high16 = eq) ----
    unsigned int gt = 0, eq = 0;
    #pragma unroll
    for (int i = 0; i < 4; i++) {
        gt += (k[i] > T);
        eq += (k[i] == T);
    }
    unsigned int pref = block_scan_excl(gt | (eq << 16), warpSums);
    unsigned int gtBefore = pref & 0xFFFFu;
    unsigned int eqBefore = pref >> 16;
    unsigned int base = gtBefore + ((eqBefore < R) ? eqBefore : R);

    // ---- emit in ascending index order ----
    const size_t idxBase = (size_t)blockIdx.x * K_;
    const float inv_n = 1.0f / (float)N_;

    unsigned int j = base, eqRank = eqBefore;
    #pragma unroll
    for (int i = 0; i < 4; i++) {
        int e = 4 * t + i;
        unsigned int kk = k[i];
        bool isEq = (kk == T);
        bool sel  = (kk > T) || (isEq && (eqRank < R));
        eqRank += isEq ? 1u : 0u;
        if (sel) {
            if (idxf) idxf[idxBase + j] = (float)e;
            if (ind)  atomicAdd(&ind[((size_t)b * K_ + j) * D_ + e], inv_n);
            j++;
        }
    }
}

extern "C" void kernel_launch(void* const* d_in, const int* in_sizes, int n_in,
                              void* d_out, int out_size) {
    const float* x     = (const float*)d_in[0];
    const float* noise = (const float*)d_in[1];
    if (n_in >= 2 && in_sizes[0] != B_ * D_) {
        x     = (const float*)d_in[1];
        noise = (const float*)d_in[0];
    }

    const long long IND = (long long)B_ * K_ * D_;   // 8388608
    const long long IDX = (long long)B_ * N_ * K_;   // 2048000

    float* ind  = nullptr;
    float* idxf = nullptr;
    if ((long long)out_size >= IND + IDX) {
        ind  = (float*)d_out;
        idxf = (float*)d_out + IND;
    } else if ((long long)out_size == IND) {
        ind = (float*)d_out;
    } else if ((long long)out_size == IDX) {
        idxf = (float*)d_out;
    } else {
        ind = (float*)d_out;
    }

    if (ind) zero_kernel<<<2048, 256>>>((float4*)ind, (int)(IND / 4));
    perturbed_topk_kernel<<<B_ * N_, THREADS>>>(x, noise, ind, idxf);
}

// round 5
// speedup vs baseline: 3.4046x; 1.2143x over previous
#include <cuda_runtime.h>
#include <cstdint>

#define B_      32
#define N_      500
#define D_      2048
#define K_      128
#define SIGMA   0.05f
#define THREADS 256          // 8 contiguous elements per thread

__device__ float g_xk[B_];   // exact (or safe lower bound of) K-th largest of x per row

// monotone float -> uint (bigger float -> bigger uint)
__device__ __forceinline__ unsigned int f2u(float f) {
    unsigned int u = __float_as_uint(f);
    return u ^ (((unsigned int)((int)u >> 31)) | 0x80000000u);
}
__device__ __forceinline__ float u2f(unsigned int u) {
    unsigned int v = (u & 0x80000000u) ? (u ^ 0x80000000u) : ~u;
    return __uint_as_float(v);
}

// exclusive block scan over 256 threads (8 warps); returns total. 16+16 packed safe.
__device__ __forceinline__ unsigned int block_scan_excl(unsigned int v,
                                                        unsigned int* warpSums,
                                                        unsigned int* total) {
    const int lane = threadIdx.x & 31;
    const int wid  = threadIdx.x >> 5;
    unsigned int x = v;
    #pragma unroll
    for (int o = 1; o < 32; o <<= 1) {
        unsigned int y = __shfl_up_sync(0xffffffffu, x, o);
        if (lane >= o) x += y;
    }
    if (lane == 31) warpSums[wid] = x;
    __syncthreads();
    if (wid == 0 && lane < 8) {
        unsigned int s = warpSums[lane];
        #pragma unroll
        for (int o = 1; o < 8; o <<= 1) {
            unsigned int y = __shfl_up_sync(0xffu, s, o);
            if (lane >= o) s += y;
        }
        warpSums[lane] = s;
    }
    __syncthreads();
    unsigned int base = (wid > 0) ? warpSums[wid - 1] : 0u;
    unsigned int tot  = warpSums[7];
    __syncthreads();
    *total = tot;
    return base + x - v;
}

__global__ void zero_kernel(float4* __restrict__ p, int n4) {
    int i = blockIdx.x * blockDim.x + threadIdx.x;
    int stride = gridDim.x * blockDim.x;
    float4 z = make_float4(0.f, 0.f, 0.f, 0.f);
    for (; i < n4; i += stride) p[i] = z;
}

// ---- pre-kernel: per row b, exact K-th largest of x (early-exit gives a
//      bin floor <= true value, which only loosens the candidate bound) ----
__global__ __launch_bounds__(THREADS)
void xk_kernel(const float* __restrict__ x) {
    __shared__ unsigned int hist[256];
    __shared__ unsigned int sh_sel, sh_krem, sh_done;

    const int t = threadIdx.x, lane = t & 31, wid = t >> 5;
    const int b = blockIdx.x;

    unsigned int k[8];
    {
        const float4* xv = (const float4*)(x + (size_t)b * D_);
        float4 a = xv[2 * t], c = xv[2 * t + 1];
        k[0] = f2u(a.x); k[1] = f2u(a.y); k[2] = f2u(a.z); k[3] = f2u(a.w);
        k[4] = f2u(c.x); k[5] = f2u(c.y); k[6] = f2u(c.z); k[7] = f2u(c.w);
    }

    unsigned int pref = 0, maskH = 0, krem = K_, done = 0;
    for (int pass = 0; pass < 4; pass++) {
        const int shift = 24 - pass * 8;
        hist[t] = 0u;
        __syncthreads();
        #pragma unroll
        for (int i = 0; i < 8; i++) {
            unsigned int kk = k[i];
            if ((kk & maskH) == pref)
                atomicAdd(&hist[(kk >> shift) & 0xFFu], 1u);
        }
        __syncthreads();
        if (wid == 0) {
            unsigned int c[8], s = 0;
            #pragma unroll
            for (int i = 0; i < 8; i++) { c[i] = hist[lane * 8 + i]; s += c[i]; }
            unsigned int xs = s;
            #pragma unroll
            for (int o = 1; o < 32; o <<= 1) {
                unsigned int y = __shfl_up_sync(0xffffffffu, xs, o);
                if (lane >= o) xs += y;
            }
            unsigned int tot = __shfl_sync(0xffffffffu, xs, 31);
            unsigned int run = xs - s;
            #pragma unroll
            for (int i = 0; i < 8; i++) {
                unsigned int sfx = tot - run, after = sfx - c[i];
                if (sfx >= krem && after < krem) {
                    sh_sel = (unsigned int)(lane * 8 + i);
                    sh_krem = krem - after;
                    sh_done = (sfx == krem);
                }
                run += c[i];
            }
        }
        __syncthreads();
        pref |= (sh_sel << shift); maskH |= (0xFFu << shift);
        krem = sh_krem; done = sh_done;
        if (done) break;
    }
    if (t == 0) g_xk[b] = u2f(pref);
}

// ---- main kernel ----
__global__ __launch_bounds__(THREADS)
void perturbed_topk_kernel(const float* __restrict__ x,
                           const float* __restrict__ noise,
                           float* __restrict__ ind,    // (B,K,D) or null
                           float* __restrict__ idxf)   // (B,N,K) or null
{
    __shared__ unsigned int  ckey[D_];
    __shared__ unsigned short cidx[D_];
    __shared__ unsigned int  hist[256];
    __shared__ unsigned int  warpSums[8];
    __shared__ float         warpMax[8];
    __shared__ float         sh_L;
    __shared__ unsigned int  sh_sel, sh_krem, sh_done;

    const int t = threadIdx.x, lane = t & 31, wid = t >> 5;
    const int b = blockIdx.x / N_;

    // load + perturb (thread t owns elems 8t..8t+7), track row max |noise|
    float kf[8];
    float am = 0.f;
    {
        const float4* xv = (const float4*)(x + (size_t)b * D_);
        const float4* nv = (const float4*)(noise + (size_t)blockIdx.x * D_);
        float4 X0 = xv[2 * t], X1 = xv[2 * t + 1];
        float4 N0 = nv[2 * t], N1 = nv[2 * t + 1];
        kf[0] = fmaf(SIGMA, N0.x, X0.x); am = fmaxf(am, fabsf(N0.x));
        kf[1] = fmaf(SIGMA, N0.y, X0.y); am = fmaxf(am, fabsf(N0.y));
        kf[2] = fmaf(SIGMA, N0.z, X0.z); am = fmaxf(am, fabsf(N0.z));
        kf[3] = fmaf(SIGMA, N0.w, X0.w); am = fmaxf(am, fabsf(N0.w));
        kf[4] = fmaf(SIGMA, N1.x, X1.x); am = fmaxf(am, fabsf(N1.x));
        kf[5] = fmaf(SIGMA, N1.y, X1.y); am = fmaxf(am, fabsf(N1.y));
        kf[6] = fmaf(SIGMA, N1.z, X1.z); am = fmaxf(am, fabsf(N1.z));
        kf[7] = fmaf(SIGMA, N1.w, X1.w); am = fmaxf(am, fabsf(N1.w));
    }
    #pragma unroll
    for (int o = 16; o > 0; o >>= 1)
        am = fmaxf(am, __shfl_xor_sync(0xffffffffu, am, o));
    if (lane == 0) warpMax[wid] = am;
    __syncthreads();
    if (t == 0) {
        float m = warpMax[0];
        #pragma unroll
        for (int w = 1; w < 8; w++) m = fmaxf(m, warpMax[w]);
        // safe lower bound on the K-th largest perturbed key (margin >> fma rounding)
        sh_L = g_xk[b] - SIGMA * m - 1e-4f;
    }
    __syncthreads();
    const unsigned int Lu = f2u(sh_L);

    // candidate mask + compaction (ascending index order preserved)
    unsigned int ku[8], m8 = 0;
    #pragma unroll
    for (int i = 0; i < 8; i++) {
        ku[i] = f2u(kf[i]);
        m8 |= (ku[i] >= Lu) ? (1u << i) : 0u;
    }
    unsigned int tot;
    unsigned int pos = block_scan_excl(__popc(m8), warpSums, &tot);
    const int cnt = (int)tot;          // >= K guaranteed, <= 2048
    unsigned int mm = m8;
    while (mm) {
        int i = __ffs(mm) - 1;
        mm &= mm - 1;
        ckey[pos] = ku[i];
        cidx[pos] = (unsigned short)(8 * t + i);
        pos++;
    }
    __syncthreads();

    // radix select over the cnt candidates (typically ~190 -> <1 per thread)
    unsigned int pref = 0, maskH = 0, krem = K_, done = 0;
    for (int pass = 0; pass < 4; pass++) {
        const int shift = 24 - pass * 8;
        hist[t] = 0u;
        __syncthreads();
        for (int i = t; i < cnt; i += THREADS) {
            unsigned int u = ckey[i];
            if ((u & maskH) == pref)
                atomicAdd(&hist[(u >> shift) & 0xFFu], 1u);
        }
        __syncthreads();
        if (wid == 0) {
            unsigned int c[8], s = 0;
            #pragma unroll
            for (int i = 0; i < 8; i++) { c[i] = hist[lane * 8 + i]; s += c[i]; }
            unsigned int xs = s;
            #pragma unroll
            for (int o = 1; o < 32; o <<= 1) {
                unsigned int y = __shfl_up_sync(0xffffffffu, xs, o);
                if (lane >= o) xs += y;
            }
            unsigned int tt = __shfl_sync(0xffffffffu, xs, 31);
            unsigned int run = xs - s;
            #pragma unroll
            for (int i = 0; i < 8; i++) {
                unsigned int sfx = tt - run, after = sfx - c[i];
                if (sfx >= krem && after < krem) {
                    sh_sel = (unsigned int)(lane * 8 + i);
                    sh_krem = krem - after;
                    sh_done = (sfx == krem);
                }
                run += c[i];
            }
        }
        __syncthreads();
        pref |= (sh_sel << shift); maskH |= (0xFFu << shift);
        krem = sh_krem; done = sh_done;
        if (done) break;
    }
    const unsigned int T = pref;
    const unsigned int R = done ? (unsigned int)K_ : krem;

    // contiguous-chunk ownership keeps array (= index) order for the rank scan
    const int ept = (cnt + THREADS - 1) / THREADS;   // usually 1
    const int beg = t * ept;
    int end = beg + ept; if (end > cnt) end = cnt;

    unsigned int gt = 0, eq = 0;
    for (int i = beg; i < end; i++) {
        unsigned int u = ckey[i];
        gt += (u > T);
        eq += (u == T);
    }
    unsigned int tot2;
    unsigned int pr = block_scan_excl(gt | (eq << 16), warpSums, &tot2);
    unsigned int gtB = pr & 0xFFFFu;
    unsigned int eqB = pr >> 16;

    unsigned int j = gtB + ((eqB < R) ? eqB : R);
    unsigned int eqRank = eqB;
    const size_t idxBase = (size_t)blockIdx.x * K_;
    const float inv_n = 1.0f / (float)N_;

    for (int i = beg; i < end; i++) {
        unsigned int u = ckey[i];
        bool isEq = (u == T);
        bool sel  = (u > T) || (isEq && (eqRank < R));
        eqRank += isEq ? 1u : 0u;
        if (sel) {
            int e = (int)cidx[i];
            if (idxf) idxf[idxBase + j] = (float)e;
            if (ind)  atomicAdd(&ind[((size_t)b * K_ + j) * D_ + e], inv_n);
            j++;
        }
    }
}

extern "C" void kernel_launch(void* const* d_in, const int* in_sizes, int n_in,
                              void* d_out, int out_size) {
    const float* x     = (const float*)d_in[0];
    const float* noise = (const float*)d_in[1];
    if (n_in >= 2 && in_sizes[0] != B_ * D_) {
        x     = (const float*)d_in[1];
        noise = (const float*)d_in[0];
    }

    const long long IND = (long long)B_ * K_ * D_;   // 8388608
    const long long IDX = (long long)B_ * N_ * K_;   // 2048000

    float* ind  = nullptr;
    float* idxf = nullptr;
    if ((long long)out_size >= IND + IDX) {
        ind  = (float*)d_out;
        idxf = (float*)d_out + IND;
    } else if ((long long)out_size == IND) {
        ind = (float*)d_out;
    } else if ((long long)out_size == IDX) {
        idxf = (float*)d_out;
    } else {
        ind = (float*)d_out;
    }

    xk_kernel<<<B_, THREADS>>>(x);
    if (ind) zero_kernel<<<2048, 256>>>((float4*)ind, (int)(IND / 4));
    perturbed_topk_kernel<<<B_ * N_, THREADS>>>(x, noise, ind, idxf);
}